// round 1
// baseline (speedup 1.0000x reference)
#include <cuda_runtime.h>
#include <cstdint>

#define S 2048
#define BB 4
#define D 1024
#define H 16
#define HD 64

// Scratch (device globals — no allocations allowed)
__device__ float g_qkv[(size_t)BB * S * 3 * D];   // 96 MB
__device__ float g_q[(size_t)BB * H * S * HD];    // 32 MB
__device__ float g_k[(size_t)BB * H * S * HD];    // 32 MB
__device__ float g_v[(size_t)BB * H * S * HD];    // 32 MB
__device__ float g_ctx[(size_t)BB * S * D];       // 32 MB

// ---------------------------------------------------------------------------
// SGEMM: C[m,n] = sum_k A[m,k] * Bw[k,n]
// M = 8192 (m = b*S + s), K = 1024.
// MODE 0: A = x laid out (S,B,D) -> A[m,k] = x[(s*B+b)*D + k]; C = qkv, N=3072
// MODE 1: A = ctx (row-major m*D);                        C = out (S,B,D), N=1024
// Block tile 128x128, K-tile 8, 256 threads, 8x8 per thread (2x2 of 4x4).
// ---------------------------------------------------------------------------
template <int MODE>
__global__ void __launch_bounds__(256) sgemm_k(const float* __restrict__ A,
                                               const float* __restrict__ Bw,
                                               float* __restrict__ C) {
    constexpr int N = (MODE == 0) ? 3 * D : D;
    constexpr int K = D;
    __shared__ float As[8][128];
    __shared__ float Bs[8][128];

    const int tid = threadIdx.x;
    const int bm = blockIdx.y, bn = blockIdx.x;

    // A tile loading: each thread loads one float4 (row tid/2, k-part (tid&1)*4)
    const int arow = tid >> 1;
    const int apart = (tid & 1) << 2;
    const int m_a = bm * 128 + arow;
    const float* Arow;
    if (MODE == 0) {
        int b = m_a >> 11, s = m_a & 2047;
        Arow = A + ((size_t)s * BB + b) * D;
    } else {
        Arow = A + (size_t)m_a * D;
    }

    // B tile loading: thread loads float4 at (k=tid/32, col=(tid&31)*4)
    const int bk = tid >> 5;
    const int bcol = (tid & 31) << 2;
    const float* Bptr = Bw + (size_t)bk * N + bn * 128 + bcol;

    const int ty = tid >> 4, tx = tid & 15;

    float acc[8][8];
#pragma unroll
    for (int i = 0; i < 8; i++)
#pragma unroll
        for (int j = 0; j < 8; j++) acc[i][j] = 0.0f;

    for (int kt = 0; kt < K; kt += 8) {
        float4 av = *(const float4*)(Arow + kt + apart);
        As[apart + 0][arow] = av.x;
        As[apart + 1][arow] = av.y;
        As[apart + 2][arow] = av.z;
        As[apart + 3][arow] = av.w;
        *(float4*)&Bs[bk][bcol] = *(const float4*)(Bptr + (size_t)kt * N);
        __syncthreads();
#pragma unroll
        for (int k = 0; k < 8; k++) {
            float a[8], bb[8];
            *(float4*)&a[0] = *(const float4*)&As[k][ty << 2];
            *(float4*)&a[4] = *(const float4*)&As[k][64 + (ty << 2)];
            *(float4*)&bb[0] = *(const float4*)&Bs[k][tx << 2];
            *(float4*)&bb[4] = *(const float4*)&Bs[k][64 + (tx << 2)];
#pragma unroll
            for (int i = 0; i < 8; i++)
#pragma unroll
                for (int j = 0; j < 8; j++) acc[i][j] += a[i] * bb[j];
        }
        __syncthreads();
    }

#pragma unroll
    for (int ih = 0; ih < 2; ih++) {
#pragma unroll
        for (int i = 0; i < 4; i++) {
            int m = bm * 128 + ih * 64 + (ty << 2) + i;
            float* crow;
            if (MODE == 0) {
                crow = C + (size_t)m * N + bn * 128;
            } else {
                int b = m >> 11, s = m & 2047;
                crow = C + ((size_t)s * BB + b) * N + bn * 128;
            }
            int r = ih * 4 + i;
            *(float4*)(crow + (tx << 2)) =
                make_float4(acc[r][0], acc[r][1], acc[r][2], acc[r][3]);
            *(float4*)(crow + 64 + (tx << 2)) =
                make_float4(acc[r][4], acc[r][5], acc[r][6], acc[r][7]);
        }
    }
}

// ---------------------------------------------------------------------------
// RoPE + split into head layout (B,H,S,HD). rotate: out[d]=x[d]*cos + rot*sin,
// rot[2i] = -x[2i+1], rot[2i+1] = x[2i]  -> partner via shfl_xor(...,1).
// ---------------------------------------------------------------------------
__global__ void rope_split(const float* __restrict__ qkv,
                           const float* __restrict__ cosb,
                           const float* __restrict__ sinb) {
    int d = threadIdx.x;                         // 0..63
    int h = blockIdx.y * blockDim.y + threadIdx.y;
    int s = blockIdx.x;
    int b = blockIdx.z;

    size_t base = ((size_t)(b * S + s)) * (3 * D) + h * HD + d;
    float q = qkv[base];
    float k = qkv[base + D];
    float v = qkv[base + 2 * D];
    float c = cosb[s * HD + d];
    float sn = sinb[s * HD + d];

    float qp = __shfl_xor_sync(0xffffffffu, q, 1);
    float kp = __shfl_xor_sync(0xffffffffu, k, 1);
    float qr = (d & 1) ? qp : -qp;
    float kr = (d & 1) ? kp : -kp;

    size_t o = ((size_t)(b * H + h) * S + s) * HD + d;
    g_q[o] = q * c + qr * sn;
    g_k[o] = k * c + kr * sn;
    g_v[o] = v;
}

// ---------------------------------------------------------------------------
// Flash attention, causal. One CTA per (q-block of 64, b*h). 256 threads.
// Score tile 64x64: thread(ty,tx) owns rows ty*4+i, cols tx*4+j.
// Smem: Qt (transposed) | Kt (transposed) | Vs (natural) | Ps (natural).
// ---------------------------------------------------------------------------
__global__ void __launch_bounds__(256) flash_kernel() {
    extern __shared__ float sm[];
    float* Qt = sm;            // [d][r]  4096
    float* Kt = sm + 4096;     // [d][t]  4096
    float* Vs = sm + 8192;     // [t][c]  4096
    float* Ps = sm + 12288;    // [r][t]  4096

    const int tid = threadIdx.x;
    const int qb = blockIdx.x;
    const int bh = blockIdx.y;
    const int ty = tid >> 4, tx = tid & 15;

    const float* Qg = g_q + ((size_t)bh * S + qb * 64) * HD;
    const float* Kg = g_k + (size_t)bh * S * HD;
    const float* Vg = g_v + (size_t)bh * S * HD;

    // Load Q transposed: Qt[d][r]
    {
        int r = tid >> 2;
        int d0 = (tid & 3) << 4;
#pragma unroll
        for (int c = 0; c < 4; c++) {
            float4 qv = *(const float4*)(Qg + r * HD + d0 + c * 4);
            Qt[(d0 + c * 4 + 0) * 64 + r] = qv.x;
            Qt[(d0 + c * 4 + 1) * 64 + r] = qv.y;
            Qt[(d0 + c * 4 + 2) * 64 + r] = qv.z;
            Qt[(d0 + c * 4 + 3) * 64 + r] = qv.w;
        }
    }

    float o[4][4];
#pragma unroll
    for (int i = 0; i < 4; i++)
#pragma unroll
        for (int j = 0; j < 4; j++) o[i][j] = 0.0f;
    float mi[4] = {-1e30f, -1e30f, -1e30f, -1e30f};
    float li[4] = {0.0f, 0.0f, 0.0f, 0.0f};

    const float scale = 0.125f;  // 1/sqrt(64)

    for (int kb = 0; kb <= qb; kb++) {
        // Load K transposed + V natural
        {
            int r = tid >> 2;
            int d0 = (tid & 3) << 4;
            const float* Kgb = Kg + (size_t)kb * 64 * HD;
#pragma unroll
            for (int c = 0; c < 4; c++) {
                float4 kv = *(const float4*)(Kgb + r * HD + d0 + c * 4);
                Kt[(d0 + c * 4 + 0) * 64 + r] = kv.x;
                Kt[(d0 + c * 4 + 1) * 64 + r] = kv.y;
                Kt[(d0 + c * 4 + 2) * 64 + r] = kv.z;
                Kt[(d0 + c * 4 + 3) * 64 + r] = kv.w;
            }
            const float4* vsrc = (const float4*)(Vg + (size_t)kb * 64 * HD);
            float4* vdst = (float4*)Vs;
#pragma unroll
            for (int i = 0; i < 4; i++) vdst[tid + i * 256] = vsrc[tid + i * 256];
        }
        __syncthreads();

        // Scores: sc[i][j] = sum_d Q[r][d]*K[t][d]
        float sc[4][4];
#pragma unroll
        for (int i = 0; i < 4; i++)
#pragma unroll
            for (int j = 0; j < 4; j++) sc[i][j] = 0.0f;
#pragma unroll 8
        for (int kk = 0; kk < 64; kk++) {
            float4 a = *(const float4*)&Qt[kk * 64 + (ty << 2)];
            float4 bb = *(const float4*)&Kt[kk * 64 + (tx << 2)];
            float av[4] = {a.x, a.y, a.z, a.w};
            float bv[4] = {bb.x, bb.y, bb.z, bb.w};
#pragma unroll
            for (int i = 0; i < 4; i++)
#pragma unroll
                for (int j = 0; j < 4; j++) sc[i][j] += av[i] * bv[j];
        }

        // Scale + causal mask (only needed on diagonal block)
        if (kb == qb) {
#pragma unroll
            for (int i = 0; i < 4; i++)
#pragma unroll
                for (int j = 0; j < 4; j++) {
                    sc[i][j] = ((tx << 2) + j > (ty << 2) + i) ? -1e30f
                                                               : sc[i][j] * scale;
                }
        } else {
#pragma unroll
            for (int i = 0; i < 4; i++)
#pragma unroll
                for (int j = 0; j < 4; j++) sc[i][j] *= scale;
        }

        // Online softmax
#pragma unroll
        for (int i = 0; i < 4; i++) {
            float mx = fmaxf(fmaxf(sc[i][0], sc[i][1]), fmaxf(sc[i][2], sc[i][3]));
            mx = fmaxf(mx, __shfl_xor_sync(0xffffffffu, mx, 1));
            mx = fmaxf(mx, __shfl_xor_sync(0xffffffffu, mx, 2));
            mx = fmaxf(mx, __shfl_xor_sync(0xffffffffu, mx, 4));
            mx = fmaxf(mx, __shfl_xor_sync(0xffffffffu, mx, 8));
            float mnew = fmaxf(mi[i], mx);
            float fac = __expf(mi[i] - mnew);
            float rs = 0.0f;
#pragma unroll
            for (int j = 0; j < 4; j++) {
                sc[i][j] = __expf(sc[i][j] - mnew);
                rs += sc[i][j];
            }
            rs += __shfl_xor_sync(0xffffffffu, rs, 1);
            rs += __shfl_xor_sync(0xffffffffu, rs, 2);
            rs += __shfl_xor_sync(0xffffffffu, rs, 4);
            rs += __shfl_xor_sync(0xffffffffu, rs, 8);
            li[i] = li[i] * fac + rs;
            mi[i] = mnew;
#pragma unroll
            for (int j = 0; j < 4; j++) o[i][j] *= fac;
            *(float4*)&Ps[((ty << 2) + i) * 64 + (tx << 2)] =
                make_float4(sc[i][0], sc[i][1], sc[i][2], sc[i][3]);
        }
        __syncthreads();

        // O += P @ V
#pragma unroll 4
        for (int t = 0; t < 64; t++) {
            float4 vv = *(const float4*)&Vs[t * 64 + (tx << 2)];
#pragma unroll
            for (int i = 0; i < 4; i++) {
                float p = Ps[((ty << 2) + i) * 64 + t];
                o[i][0] += p * vv.x;
                o[i][1] += p * vv.y;
                o[i][2] += p * vv.z;
                o[i][3] += p * vv.w;
            }
        }
        __syncthreads();
    }

    // Normalize + write ctx (B, S, D) with column offset h*HD
    int b = bh >> 4;
    int h = bh & 15;
#pragma unroll
    for (int i = 0; i < 4; i++) {
        int srow = qb * 64 + (ty << 2) + i;
        float inv = 1.0f / li[i];
        float4 r = make_float4(o[i][0] * inv, o[i][1] * inv, o[i][2] * inv,
                               o[i][3] * inv);
        *(float4*)&g_ctx[((size_t)(b * S + srow)) * D + h * HD + (tx << 2)] = r;
    }
}

// ---------------------------------------------------------------------------
extern "C" void kernel_launch(void* const* d_in, const int* in_sizes, int n_in,
                              void* d_out, int out_size) {
    (void)in_sizes; (void)n_in; (void)out_size;
    const float* x    = (const float*)d_in[0];
    // d_in[1] = attn_mask (pure causal -1e9; applied analytically)
    const float* cosb = (const float*)d_in[2];
    const float* sinb = (const float*)d_in[3];
    const float* Wqkv = (const float*)d_in[4];
    const float* Wout = (const float*)d_in[5];
    float* out = (float*)d_out;

    float *qkvp, *ctxp;
    cudaGetSymbolAddress((void**)&qkvp, g_qkv);
    cudaGetSymbolAddress((void**)&ctxp, g_ctx);

    cudaFuncSetAttribute(flash_kernel,
                         cudaFuncAttributeMaxDynamicSharedMemorySize, 65536);

    // 1) QKV projection
    sgemm_k<0><<<dim3(24, 64), 256>>>(x, Wqkv, qkvp);
    // 2) RoPE + head reshape
    rope_split<<<dim3(S, H / 4, BB), dim3(64, 4)>>>(qkvp, cosb, sinb);
    // 3) Causal flash attention
    flash_kernel<<<dim3(S / 64, BB * H), 256, 65536>>>();
    // 4) Output projection -> (S, B, D)
    sgemm_k<1><<<dim3(8, 64), 256>>>(ctxp, Wout, out);
}

// round 2
// speedup vs baseline: 1.5630x; 1.5630x over previous
#include <cuda_runtime.h>
#include <cstdint>

#define S 2048
#define BB 4
#define D 1024
#define H 16
#define HD 64

// Scratch (device globals — no allocations allowed)
__device__ float g_qkv[(size_t)BB * S * 3 * D];   // 96 MB
__device__ float g_q[(size_t)BB * H * S * HD];    // 32 MB
__device__ float g_k[(size_t)BB * H * S * HD];    // 32 MB
__device__ float g_v[(size_t)BB * H * S * HD];    // 32 MB
__device__ float g_ctx[(size_t)BB * S * D];       // 32 MB

// ---------------------------------------------------------------------------
// TF32 helpers
// ---------------------------------------------------------------------------
__device__ __forceinline__ float tf32r(float x) {
    uint32_t u;
    asm("cvt.rna.tf32.f32 %0, %1;" : "=r"(u) : "f"(x));
    return __uint_as_float(u);
}

__device__ __forceinline__ void mma_tf32(float* c, const uint32_t* a,
                                         const uint32_t* b) {
    asm volatile(
        "mma.sync.aligned.m16n8k8.row.col.f32.tf32.tf32.f32 "
        "{%0,%1,%2,%3},{%4,%5,%6,%7},{%8,%9},{%0,%1,%2,%3};"
        : "+f"(c[0]), "+f"(c[1]), "+f"(c[2]), "+f"(c[3])
        : "r"(a[0]), "r"(a[1]), "r"(a[2]), "r"(a[3]), "r"(b[0]), "r"(b[1]));
}

// ---------------------------------------------------------------------------
// TF32 tensor-core GEMM: C[m,n] = sum_k A[m,k] * Bw[k,n],  M=8192, K=1024
// MODE 0: A = x (S,B,D) -> A[m,k] = x[(s*B+b)*D+k] with m=b*S+s; C row-major, N=3072
// MODE 1: A row-major m*D; C = out (S,B,D), N=1024
// Block 128x128, BK=16, 256 threads (8 warps, warp tile 32m x 64n),
// double-buffered smem, register-staged prefetch.
// ---------------------------------------------------------------------------
template <int MODE>
__global__ void __launch_bounds__(256, 2) tgemm(const float* __restrict__ A,
                                                const float* __restrict__ Bw,
                                                float* __restrict__ C) {
    constexpr int N = (MODE == 0) ? 3 * D : D;
    constexpr int K = D;

    __shared__ float As[2][128][20];   // pitch 20: frag banks 4*grp+q4 distinct
    __shared__ float Bs[2][16][136];   // pitch 136: frag banks 8*q4+grp distinct

    const int tid = threadIdx.x;
    const int bm = blockIdx.y, bn = blockIdx.x;
    const int lane = tid & 31, wid = tid >> 5;
    const int grp = lane >> 2, q4 = lane & 3;
    const int wm = (wid & 3) * 32;   // 4 warps along m
    const int wn = (wid >> 2) * 64;  // 2 warps along n

    // Global A load mapping: thread -> (row=tid/2, kquad=(tid&1)*4), 2 float4/tile
    const int arow = tid >> 1;
    const int ak = (tid & 1) << 2;
    const int m_a = bm * 128 + arow;
    const float* Ag;
    if (MODE == 0) {
        int b = m_a >> 11, s = m_a & 2047;
        Ag = A + ((size_t)s * BB + b) * D;
    } else {
        Ag = A + (size_t)m_a * D;
    }

    // Global B load mapping: thread -> (k=tid/32 (+8), col=(tid&31)*4)
    const int bkr = tid >> 5;
    const int bcol = (tid & 31) << 2;
    const float* Bg = Bw + (size_t)bkr * N + bn * 128 + bcol;

    float acc[2][8][4];
#pragma unroll
    for (int i = 0; i < 2; i++)
#pragma unroll
        for (int j = 0; j < 8; j++)
#pragma unroll
            for (int l = 0; l < 4; l++) acc[i][j][l] = 0.0f;

    // Prologue: tile 0 -> buffer 0
    {
        float4 a0 = *(const float4*)(Ag + ak);
        float4 a1 = *(const float4*)(Ag + ak + 8);
        float4 b0 = *(const float4*)(Bg);
        float4 b1 = *(const float4*)(Bg + (size_t)8 * N);
        As[0][arow][ak + 0] = tf32r(a0.x);
        As[0][arow][ak + 1] = tf32r(a0.y);
        As[0][arow][ak + 2] = tf32r(a0.z);
        As[0][arow][ak + 3] = tf32r(a0.w);
        As[0][arow][ak + 8] = tf32r(a1.x);
        As[0][arow][ak + 9] = tf32r(a1.y);
        As[0][arow][ak + 10] = tf32r(a1.z);
        As[0][arow][ak + 11] = tf32r(a1.w);
        Bs[0][bkr][bcol + 0] = tf32r(b0.x);
        Bs[0][bkr][bcol + 1] = tf32r(b0.y);
        Bs[0][bkr][bcol + 2] = tf32r(b0.z);
        Bs[0][bkr][bcol + 3] = tf32r(b0.w);
        Bs[0][bkr + 8][bcol + 0] = tf32r(b1.x);
        Bs[0][bkr + 8][bcol + 1] = tf32r(b1.y);
        Bs[0][bkr + 8][bcol + 2] = tf32r(b1.z);
        Bs[0][bkr + 8][bcol + 3] = tf32r(b1.w);
    }
    __syncthreads();

    int buf = 0;
    for (int kt = 0; kt < K; kt += 16) {
        float4 pa0, pa1, pb0, pb1;
        const bool pf = (kt + 16) < K;
        if (pf) {
            pa0 = *(const float4*)(Ag + kt + 16 + ak);
            pa1 = *(const float4*)(Ag + kt + 16 + ak + 8);
            pb0 = *(const float4*)(Bg + (size_t)(kt + 16) * N);
            pb1 = *(const float4*)(Bg + (size_t)(kt + 24) * N);
        }

        // Compute on current buffer
#pragma unroll
        for (int ks = 0; ks < 2; ks++) {
            const int k0 = ks * 8;
            uint32_t a[2][4], b[8][2];
#pragma unroll
            for (int ma = 0; ma < 2; ma++) {
                int r = wm + ma * 16 + grp;
                a[ma][0] = __float_as_uint(As[buf][r][k0 + q4]);
                a[ma][1] = __float_as_uint(As[buf][r + 8][k0 + q4]);
                a[ma][2] = __float_as_uint(As[buf][r][k0 + q4 + 4]);
                a[ma][3] = __float_as_uint(As[buf][r + 8][k0 + q4 + 4]);
            }
#pragma unroll
            for (int na = 0; na < 8; na++) {
                int c = wn + na * 8 + grp;
                b[na][0] = __float_as_uint(Bs[buf][k0 + q4][c]);
                b[na][1] = __float_as_uint(Bs[buf][k0 + q4 + 4][c]);
            }
#pragma unroll
            for (int ma = 0; ma < 2; ma++)
#pragma unroll
                for (int na = 0; na < 8; na++) mma_tf32(acc[ma][na], a[ma], b[na]);
        }

        if (pf) {
            const int nb = buf ^ 1;
            As[nb][arow][ak + 0] = tf32r(pa0.x);
            As[nb][arow][ak + 1] = tf32r(pa0.y);
            As[nb][arow][ak + 2] = tf32r(pa0.z);
            As[nb][arow][ak + 3] = tf32r(pa0.w);
            As[nb][arow][ak + 8] = tf32r(pa1.x);
            As[nb][arow][ak + 9] = tf32r(pa1.y);
            As[nb][arow][ak + 10] = tf32r(pa1.z);
            As[nb][arow][ak + 11] = tf32r(pa1.w);
            Bs[nb][bkr][bcol + 0] = tf32r(pb0.x);
            Bs[nb][bkr][bcol + 1] = tf32r(pb0.y);
            Bs[nb][bkr][bcol + 2] = tf32r(pb0.z);
            Bs[nb][bkr][bcol + 3] = tf32r(pb0.w);
            Bs[nb][bkr + 8][bcol + 0] = tf32r(pb1.x);
            Bs[nb][bkr + 8][bcol + 1] = tf32r(pb1.y);
            Bs[nb][bkr + 8][bcol + 2] = tf32r(pb1.z);
            Bs[nb][bkr + 8][bcol + 3] = tf32r(pb1.w);
        }
        __syncthreads();
        buf ^= 1;
    }

    // Epilogue: c0=(grp,2q4) c1=(grp,2q4+1) c2=(grp+8,2q4) c3=(grp+8,2q4+1)
#pragma unroll
    for (int ma = 0; ma < 2; ma++) {
#pragma unroll
        for (int half = 0; half < 2; half++) {
            int r = bm * 128 + wm + ma * 16 + grp + half * 8;
            float* crow;
            if (MODE == 0) {
                crow = C + (size_t)r * N;
            } else {
                int b = r >> 11, s = r & 2047;
                crow = C + ((size_t)s * BB + b) * D;
            }
#pragma unroll
            for (int na = 0; na < 8; na++) {
                int col = bn * 128 + wn + na * 8 + (q4 << 1);
                float2 v;
                v.x = acc[ma][na][half * 2 + 0];
                v.y = acc[ma][na][half * 2 + 1];
                *(float2*)(crow + col) = v;
            }
        }
    }
}

// ---------------------------------------------------------------------------
// RoPE + split into head layout (B,H,S,HD). (unchanged)
// ---------------------------------------------------------------------------
__global__ void rope_split(const float* __restrict__ qkv,
                           const float* __restrict__ cosb,
                           const float* __restrict__ sinb) {
    int d = threadIdx.x;
    int h = blockIdx.y * blockDim.y + threadIdx.y;
    int s = blockIdx.x;
    int b = blockIdx.z;

    size_t base = ((size_t)(b * S + s)) * (3 * D) + h * HD + d;
    float q = qkv[base];
    float k = qkv[base + D];
    float v = qkv[base + 2 * D];
    float c = cosb[s * HD + d];
    float sn = sinb[s * HD + d];

    float qp = __shfl_xor_sync(0xffffffffu, q, 1);
    float kp = __shfl_xor_sync(0xffffffffu, k, 1);
    float qr = (d & 1) ? qp : -qp;
    float kr = (d & 1) ? kp : -kp;

    size_t o = ((size_t)(b * H + h) * S + s) * HD + d;
    g_q[o] = q * c + qr * sn;
    g_k[o] = k * c + kr * sn;
    g_v[o] = v;
}

// ---------------------------------------------------------------------------
// Flash attention, causal. (unchanged from passing R1)
// ---------------------------------------------------------------------------
__global__ void __launch_bounds__(256) flash_kernel() {
    extern __shared__ float sm[];
    float* Qt = sm;            // [d][r]  4096
    float* Kt = sm + 4096;     // [d][t]  4096
    float* Vs = sm + 8192;     // [t][c]  4096
    float* Ps = sm + 12288;    // [r][t]  4096

    const int tid = threadIdx.x;
    const int qb = blockIdx.x;
    const int bh = blockIdx.y;
    const int ty = tid >> 4, tx = tid & 15;

    const float* Qg = g_q + ((size_t)bh * S + qb * 64) * HD;
    const float* Kg = g_k + (size_t)bh * S * HD;
    const float* Vg = g_v + (size_t)bh * S * HD;

    {
        int r = tid >> 2;
        int d0 = (tid & 3) << 4;
#pragma unroll
        for (int c = 0; c < 4; c++) {
            float4 qv = *(const float4*)(Qg + r * HD + d0 + c * 4);
            Qt[(d0 + c * 4 + 0) * 64 + r] = qv.x;
            Qt[(d0 + c * 4 + 1) * 64 + r] = qv.y;
            Qt[(d0 + c * 4 + 2) * 64 + r] = qv.z;
            Qt[(d0 + c * 4 + 3) * 64 + r] = qv.w;
        }
    }

    float o[4][4];
#pragma unroll
    for (int i = 0; i < 4; i++)
#pragma unroll
        for (int j = 0; j < 4; j++) o[i][j] = 0.0f;
    float mi[4] = {-1e30f, -1e30f, -1e30f, -1e30f};
    float li[4] = {0.0f, 0.0f, 0.0f, 0.0f};

    const float scale = 0.125f;

    for (int kb = 0; kb <= qb; kb++) {
        {
            int r = tid >> 2;
            int d0 = (tid & 3) << 4;
            const float* Kgb = Kg + (size_t)kb * 64 * HD;
#pragma unroll
            for (int c = 0; c < 4; c++) {
                float4 kv = *(const float4*)(Kgb + r * HD + d0 + c * 4);
                Kt[(d0 + c * 4 + 0) * 64 + r] = kv.x;
                Kt[(d0 + c * 4 + 1) * 64 + r] = kv.y;
                Kt[(d0 + c * 4 + 2) * 64 + r] = kv.z;
                Kt[(d0 + c * 4 + 3) * 64 + r] = kv.w;
            }
            const float4* vsrc = (const float4*)(Vg + (size_t)kb * 64 * HD);
            float4* vdst = (float4*)Vs;
#pragma unroll
            for (int i = 0; i < 4; i++) vdst[tid + i * 256] = vsrc[tid + i * 256];
        }
        __syncthreads();

        float sc[4][4];
#pragma unroll
        for (int i = 0; i < 4; i++)
#pragma unroll
            for (int j = 0; j < 4; j++) sc[i][j] = 0.0f;
#pragma unroll 8
        for (int kk = 0; kk < 64; kk++) {
            float4 a = *(const float4*)&Qt[kk * 64 + (ty << 2)];
            float4 bb = *(const float4*)&Kt[kk * 64 + (tx << 2)];
            float av[4] = {a.x, a.y, a.z, a.w};
            float bv[4] = {bb.x, bb.y, bb.z, bb.w};
#pragma unroll
            for (int i = 0; i < 4; i++)
#pragma unroll
                for (int j = 0; j < 4; j++) sc[i][j] += av[i] * bv[j];
        }

        if (kb == qb) {
#pragma unroll
            for (int i = 0; i < 4; i++)
#pragma unroll
                for (int j = 0; j < 4; j++) {
                    sc[i][j] = ((tx << 2) + j > (ty << 2) + i) ? -1e30f
                                                               : sc[i][j] * scale;
                }
        } else {
#pragma unroll
            for (int i = 0; i < 4; i++)
#pragma unroll
                for (int j = 0; j < 4; j++) sc[i][j] *= scale;
        }

#pragma unroll
        for (int i = 0; i < 4; i++) {
            float mx = fmaxf(fmaxf(sc[i][0], sc[i][1]), fmaxf(sc[i][2], sc[i][3]));
            mx = fmaxf(mx, __shfl_xor_sync(0xffffffffu, mx, 1));
            mx = fmaxf(mx, __shfl_xor_sync(0xffffffffu, mx, 2));
            mx = fmaxf(mx, __shfl_xor_sync(0xffffffffu, mx, 4));
            mx = fmaxf(mx, __shfl_xor_sync(0xffffffffu, mx, 8));
            float mnew = fmaxf(mi[i], mx);
            float fac = __expf(mi[i] - mnew);
            float rs = 0.0f;
#pragma unroll
            for (int j = 0; j < 4; j++) {
                sc[i][j] = __expf(sc[i][j] - mnew);
                rs += sc[i][j];
            }
            rs += __shfl_xor_sync(0xffffffffu, rs, 1);
            rs += __shfl_xor_sync(0xffffffffu, rs, 2);
            rs += __shfl_xor_sync(0xffffffffu, rs, 4);
            rs += __shfl_xor_sync(0xffffffffu, rs, 8);
            li[i] = li[i] * fac + rs;
            mi[i] = mnew;
#pragma unroll
            for (int j = 0; j < 4; j++) o[i][j] *= fac;
            *(float4*)&Ps[((ty << 2) + i) * 64 + (tx << 2)] =
                make_float4(sc[i][0], sc[i][1], sc[i][2], sc[i][3]);
        }
        __syncthreads();

#pragma unroll 4
        for (int t = 0; t < 64; t++) {
            float4 vv = *(const float4*)&Vs[t * 64 + (tx << 2)];
#pragma unroll
            for (int i = 0; i < 4; i++) {
                float p = Ps[((ty << 2) + i) * 64 + t];
                o[i][0] += p * vv.x;
                o[i][1] += p * vv.y;
                o[i][2] += p * vv.z;
                o[i][3] += p * vv.w;
            }
        }
        __syncthreads();
    }

    int b = bh >> 4;
    int h = bh & 15;
#pragma unroll
    for (int i = 0; i < 4; i++) {
        int srow = qb * 64 + (ty << 2) + i;
        float inv = 1.0f / li[i];
        float4 r = make_float4(o[i][0] * inv, o[i][1] * inv, o[i][2] * inv,
                               o[i][3] * inv);
        *(float4*)&g_ctx[((size_t)(b * S + srow)) * D + h * HD + (tx << 2)] = r;
    }
}

// ---------------------------------------------------------------------------
extern "C" void kernel_launch(void* const* d_in, const int* in_sizes, int n_in,
                              void* d_out, int out_size) {
    (void)in_sizes; (void)n_in; (void)out_size;
    const float* x    = (const float*)d_in[0];
    // d_in[1] = attn_mask (pure causal; applied analytically)
    const float* cosb = (const float*)d_in[2];
    const float* sinb = (const float*)d_in[3];
    const float* Wqkv = (const float*)d_in[4];
    const float* Wout = (const float*)d_in[5];
    float* out = (float*)d_out;

    float *qkvp, *ctxp;
    cudaGetSymbolAddress((void**)&qkvp, g_qkv);
    cudaGetSymbolAddress((void**)&ctxp, g_ctx);

    cudaFuncSetAttribute(flash_kernel,
                         cudaFuncAttributeMaxDynamicSharedMemorySize, 65536);

    // 1) QKV projection (TF32 tensor cores)
    tgemm<0><<<dim3(24, 64), 256>>>(x, Wqkv, qkvp);
    // 2) RoPE + head reshape
    rope_split<<<dim3(S, H / 4, BB), dim3(64, 4)>>>(qkvp, cosb, sinb);
    // 3) Causal flash attention
    flash_kernel<<<dim3(S / 64, BB * H), 256, 65536>>>();
    // 4) Output projection (TF32 tensor cores) -> (S, B, D)
    tgemm<1><<<dim3(8, 64), 256>>>(ctxp, Wout, out);
}

// round 3
// speedup vs baseline: 1.6515x; 1.0566x over previous
#include <cuda_runtime.h>
#include <cstdint>

#define S 2048
#define BB 4
#define D 1024
#define H 16
#define HD 64

// Scratch (device globals — no allocations allowed)
__device__ float g_qkv[(size_t)BB * S * 3 * D];   // 96 MB
__device__ float g_q[(size_t)BB * H * S * HD];    // 32 MB
__device__ float g_k[(size_t)BB * H * S * HD];    // 32 MB
__device__ float g_v[(size_t)BB * H * S * HD];    // 32 MB
__device__ float g_ctx[(size_t)BB * S * D];       // 32 MB

// ---------------------------------------------------------------------------
// TF32 helpers
// ---------------------------------------------------------------------------
__device__ __forceinline__ float tf32r(float x) {
    uint32_t u;
    asm("cvt.rna.tf32.f32 %0, %1;" : "=r"(u) : "f"(x));
    return __uint_as_float(u);
}

__device__ __forceinline__ void mma_tf32(float* c, const uint32_t* a,
                                         const uint32_t* b) {
    asm volatile(
        "mma.sync.aligned.m16n8k8.row.col.f32.tf32.tf32.f32 "
        "{%0,%1,%2,%3},{%4,%5,%6,%7},{%8,%9},{%0,%1,%2,%3};"
        : "+f"(c[0]), "+f"(c[1]), "+f"(c[2]), "+f"(c[3])
        : "r"(a[0]), "r"(a[1]), "r"(a[2]), "r"(a[3]), "r"(b[0]), "r"(b[1]));
}

// ---------------------------------------------------------------------------
// TF32 tensor-core GEMM (unchanged from R2 passing kernel)
// ---------------------------------------------------------------------------
template <int MODE>
__global__ void __launch_bounds__(256, 2) tgemm(const float* __restrict__ A,
                                                const float* __restrict__ Bw,
                                                float* __restrict__ C) {
    constexpr int N = (MODE == 0) ? 3 * D : D;
    constexpr int K = D;

    __shared__ float As[2][128][20];
    __shared__ float Bs[2][16][136];

    const int tid = threadIdx.x;
    const int bm = blockIdx.y, bn = blockIdx.x;
    const int lane = tid & 31, wid = tid >> 5;
    const int grp = lane >> 2, q4 = lane & 3;
    const int wm = (wid & 3) * 32;
    const int wn = (wid >> 2) * 64;

    const int arow = tid >> 1;
    const int ak = (tid & 1) << 2;
    const int m_a = bm * 128 + arow;
    const float* Ag;
    if (MODE == 0) {
        int b = m_a >> 11, s = m_a & 2047;
        Ag = A + ((size_t)s * BB + b) * D;
    } else {
        Ag = A + (size_t)m_a * D;
    }

    const int bkr = tid >> 5;
    const int bcol = (tid & 31) << 2;
    const float* Bg = Bw + (size_t)bkr * N + bn * 128 + bcol;

    float acc[2][8][4];
#pragma unroll
    for (int i = 0; i < 2; i++)
#pragma unroll
        for (int j = 0; j < 8; j++)
#pragma unroll
            for (int l = 0; l < 4; l++) acc[i][j][l] = 0.0f;

    {
        float4 a0 = *(const float4*)(Ag + ak);
        float4 a1 = *(const float4*)(Ag + ak + 8);
        float4 b0 = *(const float4*)(Bg);
        float4 b1 = *(const float4*)(Bg + (size_t)8 * N);
        As[0][arow][ak + 0] = tf32r(a0.x);
        As[0][arow][ak + 1] = tf32r(a0.y);
        As[0][arow][ak + 2] = tf32r(a0.z);
        As[0][arow][ak + 3] = tf32r(a0.w);
        As[0][arow][ak + 8] = tf32r(a1.x);
        As[0][arow][ak + 9] = tf32r(a1.y);
        As[0][arow][ak + 10] = tf32r(a1.z);
        As[0][arow][ak + 11] = tf32r(a1.w);
        Bs[0][bkr][bcol + 0] = tf32r(b0.x);
        Bs[0][bkr][bcol + 1] = tf32r(b0.y);
        Bs[0][bkr][bcol + 2] = tf32r(b0.z);
        Bs[0][bkr][bcol + 3] = tf32r(b0.w);
        Bs[0][bkr + 8][bcol + 0] = tf32r(b1.x);
        Bs[0][bkr + 8][bcol + 1] = tf32r(b1.y);
        Bs[0][bkr + 8][bcol + 2] = tf32r(b1.z);
        Bs[0][bkr + 8][bcol + 3] = tf32r(b1.w);
    }
    __syncthreads();

    int buf = 0;
    for (int kt = 0; kt < K; kt += 16) {
        float4 pa0, pa1, pb0, pb1;
        const bool pf = (kt + 16) < K;
        if (pf) {
            pa0 = *(const float4*)(Ag + kt + 16 + ak);
            pa1 = *(const float4*)(Ag + kt + 16 + ak + 8);
            pb0 = *(const float4*)(Bg + (size_t)(kt + 16) * N);
            pb1 = *(const float4*)(Bg + (size_t)(kt + 24) * N);
        }

#pragma unroll
        for (int ks = 0; ks < 2; ks++) {
            const int k0 = ks * 8;
            uint32_t a[2][4], b[8][2];
#pragma unroll
            for (int ma = 0; ma < 2; ma++) {
                int r = wm + ma * 16 + grp;
                a[ma][0] = __float_as_uint(As[buf][r][k0 + q4]);
                a[ma][1] = __float_as_uint(As[buf][r + 8][k0 + q4]);
                a[ma][2] = __float_as_uint(As[buf][r][k0 + q4 + 4]);
                a[ma][3] = __float_as_uint(As[buf][r + 8][k0 + q4 + 4]);
            }
#pragma unroll
            for (int na = 0; na < 8; na++) {
                int c = wn + na * 8 + grp;
                b[na][0] = __float_as_uint(Bs[buf][k0 + q4][c]);
                b[na][1] = __float_as_uint(Bs[buf][k0 + q4 + 4][c]);
            }
#pragma unroll
            for (int ma = 0; ma < 2; ma++)
#pragma unroll
                for (int na = 0; na < 8; na++) mma_tf32(acc[ma][na], a[ma], b[na]);
        }

        if (pf) {
            const int nb = buf ^ 1;
            As[nb][arow][ak + 0] = tf32r(pa0.x);
            As[nb][arow][ak + 1] = tf32r(pa0.y);
            As[nb][arow][ak + 2] = tf32r(pa0.z);
            As[nb][arow][ak + 3] = tf32r(pa0.w);
            As[nb][arow][ak + 8] = tf32r(pa1.x);
            As[nb][arow][ak + 9] = tf32r(pa1.y);
            As[nb][arow][ak + 10] = tf32r(pa1.z);
            As[nb][arow][ak + 11] = tf32r(pa1.w);
            Bs[nb][bkr][bcol + 0] = tf32r(pb0.x);
            Bs[nb][bkr][bcol + 1] = tf32r(pb0.y);
            Bs[nb][bkr][bcol + 2] = tf32r(pb0.z);
            Bs[nb][bkr][bcol + 3] = tf32r(pb0.w);
            Bs[nb][bkr + 8][bcol + 0] = tf32r(pb1.x);
            Bs[nb][bkr + 8][bcol + 1] = tf32r(pb1.y);
            Bs[nb][bkr + 8][bcol + 2] = tf32r(pb1.z);
            Bs[nb][bkr + 8][bcol + 3] = tf32r(pb1.w);
        }
        __syncthreads();
        buf ^= 1;
    }

#pragma unroll
    for (int ma = 0; ma < 2; ma++) {
#pragma unroll
        for (int half = 0; half < 2; half++) {
            int r = bm * 128 + wm + ma * 16 + grp + half * 8;
            float* crow;
            if (MODE == 0) {
                crow = C + (size_t)r * N;
            } else {
                int b = r >> 11, s = r & 2047;
                crow = C + ((size_t)s * BB + b) * D;
            }
#pragma unroll
            for (int na = 0; na < 8; na++) {
                int col = bn * 128 + wn + na * 8 + (q4 << 1);
                float2 v;
                v.x = acc[ma][na][half * 2 + 0];
                v.y = acc[ma][na][half * 2 + 1];
                *(float2*)(crow + col) = v;
            }
        }
    }
}

// ---------------------------------------------------------------------------
// RoPE + split into head layout (B,H,S,HD). (unchanged)
// ---------------------------------------------------------------------------
__global__ void rope_split(const float* __restrict__ qkv,
                           const float* __restrict__ cosb,
                           const float* __restrict__ sinb) {
    int d = threadIdx.x;
    int h = blockIdx.y * blockDim.y + threadIdx.y;
    int s = blockIdx.x;
    int b = blockIdx.z;

    size_t base = ((size_t)(b * S + s)) * (3 * D) + h * HD + d;
    float q = qkv[base];
    float k = qkv[base + D];
    float v = qkv[base + 2 * D];
    float c = cosb[s * HD + d];
    float sn = sinb[s * HD + d];

    float qp = __shfl_xor_sync(0xffffffffu, q, 1);
    float kp = __shfl_xor_sync(0xffffffffu, k, 1);
    float qr = (d & 1) ? qp : -qp;
    float kr = (d & 1) ? kp : -kp;

    size_t o = ((size_t)(b * H + h) * S + s) * HD + d;
    g_q[o] = q * c + qr * sn;
    g_k[o] = k * c + kr * sn;
    g_v[o] = v;
}

// ---------------------------------------------------------------------------
// Tensor-core flash attention, causal, 3xTF32 (split hi/lo) for QK^T and PV.
// CTA: 128 q-rows x 64-key tiles, 8 warps, warp owns 16 rows (full row stats).
// Smem pitches: A-operands (Q,P) pitch 68; K (k-major) pitch 72; V (n-major)
// pitch 68 — all fragment LDS bank-conflict-free.
// ---------------------------------------------------------------------------
#define OQH 0
#define OQL 8704
#define OKH 17408
#define OKL 22016
#define OVH 26624
#define OVL 30976
#define OPH 35328
#define OPL 44032
#define FSMEM_FLOATS 52736  // 210944 bytes

__global__ void __launch_bounds__(256) flash2() {
    extern __shared__ float sm[];
    float* Qh = sm + OQH;
    float* Ql = sm + OQL;
    float* Kh = sm + OKH;
    float* Kl = sm + OKL;
    float* Vh = sm + OVH;
    float* Vl = sm + OVL;
    float* Ph = sm + OPH;
    float* Pl = sm + OPL;

    const int tid = threadIdx.x;
    const int qb = (int)(gridDim.x - 1) - (int)blockIdx.x;  // heavy CTAs first
    const int bh = blockIdx.y;
    const int lane = tid & 31, w = tid >> 5;
    const int grp = lane >> 2, q4 = lane & 3;

    const float* Qg = g_q + ((size_t)bh * S + (size_t)qb * 128) * HD;
    const float* Kg = g_k + (size_t)bh * S * HD;
    const float* Vg = g_v + (size_t)bh * S * HD;

    // ---- Q fill: scale by 1/8 (exact), split hi/lo ----
    {
        int r = tid >> 1;
        int c0 = (tid & 1) * 32;
        const float* qrow = Qg + r * HD + c0;
#pragma unroll
        for (int c = 0; c < 32; c += 4) {
            float4 qv = *(const float4*)(qrow + c);
            float f[4] = {qv.x, qv.y, qv.z, qv.w};
#pragma unroll
            for (int j = 0; j < 4; j++) {
                float x = f[j] * 0.125f;
                float hi = tf32r(x);
                Qh[r * 68 + c0 + c + j] = hi;
                Ql[r * 68 + c0 + c + j] = tf32r(x - hi);
            }
        }
    }

    float accO[8][4];
#pragma unroll
    for (int na = 0; na < 8; na++)
#pragma unroll
        for (int j = 0; j < 4; j++) accO[na][j] = 0.0f;
    float mi[2] = {-1e30f, -1e30f};
    float li[2] = {0.0f, 0.0f};

    const int ktrow = tid & 63;  // K/V fill: 32 consecutive rows per warp
    const int kdg = tid >> 6;    // d-group 0..3
    const int r0 = w * 16 + grp; // warp-local A row

    const int nkt = 2 * qb + 2;
    for (int kb = 0; kb < nkt; kb++) {
        __syncthreads();  // prev-iter PV reads of K/V done

        // ---- K/V tile fill + split ----
        {
            const float* Kp = Kg + ((size_t)kb * 64 + ktrow) * HD + kdg * 16;
            const float* Vp = Vg + ((size_t)kb * 64 + ktrow) * HD + kdg * 16;
#pragma unroll
            for (int c = 0; c < 16; c += 4) {
                float4 kv = *(const float4*)(Kp + c);
                float4 vv = *(const float4*)(Vp + c);
                float kf[4] = {kv.x, kv.y, kv.z, kv.w};
                float vf[4] = {vv.x, vv.y, vv.z, vv.w};
#pragma unroll
                for (int j = 0; j < 4; j++) {
                    int d = kdg * 16 + c + j;
                    float khi = tf32r(kf[j]);
                    Kh[d * 72 + ktrow] = khi;
                    Kl[d * 72 + ktrow] = tf32r(kf[j] - khi);
                    float vhi = tf32r(vf[j]);
                    Vh[d * 68 + ktrow] = vhi;
                    Vl[d * 68 + ktrow] = tf32r(vf[j] - vhi);
                }
            }
        }
        __syncthreads();  // K/V (and first-iter Q) ready

        // ---- QK^T (3xTF32) ----
        float accS[8][4];
#pragma unroll
        for (int na = 0; na < 8; na++)
#pragma unroll
            for (int j = 0; j < 4; j++) accS[na][j] = 0.0f;

#pragma unroll
        for (int ks = 0; ks < 8; ks++) {
            const int k0 = ks * 8;
            uint32_t ah[4], al[4];
            ah[0] = __float_as_uint(Qh[r0 * 68 + k0 + q4]);
            ah[1] = __float_as_uint(Qh[(r0 + 8) * 68 + k0 + q4]);
            ah[2] = __float_as_uint(Qh[r0 * 68 + k0 + q4 + 4]);
            ah[3] = __float_as_uint(Qh[(r0 + 8) * 68 + k0 + q4 + 4]);
            al[0] = __float_as_uint(Ql[r0 * 68 + k0 + q4]);
            al[1] = __float_as_uint(Ql[(r0 + 8) * 68 + k0 + q4]);
            al[2] = __float_as_uint(Ql[r0 * 68 + k0 + q4 + 4]);
            al[3] = __float_as_uint(Ql[(r0 + 8) * 68 + k0 + q4 + 4]);
#pragma unroll
            for (int na = 0; na < 8; na++) {
                int t = 8 * na + grp;
                uint32_t bh2[2], bl2[2];
                bh2[0] = __float_as_uint(Kh[(k0 + q4) * 72 + t]);
                bh2[1] = __float_as_uint(Kh[(k0 + q4 + 4) * 72 + t]);
                bl2[0] = __float_as_uint(Kl[(k0 + q4) * 72 + t]);
                bl2[1] = __float_as_uint(Kl[(k0 + q4 + 4) * 72 + t]);
                mma_tf32(accS[na], ah, bh2);
                mma_tf32(accS[na], ah, bl2);
                mma_tf32(accS[na], al, bh2);
            }
        }

        // ---- causal mask ----
        const int rowg0 = qb * 128 + r0;
        const int colbase = kb * 64;
        if (colbase + 63 > rowg0) {
#pragma unroll
            for (int na = 0; na < 8; na++) {
#pragma unroll
                for (int j = 0; j < 2; j++) {
                    int col = colbase + 8 * na + 2 * q4 + j;
                    if (col > rowg0) accS[na][j] = -1e30f;
                    if (col > rowg0 + 8) accS[na][2 + j] = -1e30f;
                }
            }
        }

        // ---- online softmax (row-local within warp quad) ----
#pragma unroll
        for (int hr = 0; hr < 2; hr++) {
            float mx = -1e30f;
#pragma unroll
            for (int na = 0; na < 8; na++)
                mx = fmaxf(mx, fmaxf(accS[na][2 * hr], accS[na][2 * hr + 1]));
            mx = fmaxf(mx, __shfl_xor_sync(0xffffffffu, mx, 1));
            mx = fmaxf(mx, __shfl_xor_sync(0xffffffffu, mx, 2));
            float mnew = fmaxf(mi[hr], mx);
            float fac = __expf(mi[hr] - mnew);
            float rs = 0.0f;
            const int pr = r0 + hr * 8;
#pragma unroll
            for (int na = 0; na < 8; na++) {
                float p0 = __expf(accS[na][2 * hr] - mnew);
                float p1 = __expf(accS[na][2 * hr + 1] - mnew);
                rs += p0 + p1;
                float h0 = tf32r(p0), h1 = tf32r(p1);
                int off = pr * 68 + 8 * na + 2 * q4;
                *(float2*)&Ph[off] = make_float2(h0, h1);
                *(float2*)&Pl[off] = make_float2(tf32r(p0 - h0), tf32r(p1 - h1));
            }
            rs += __shfl_xor_sync(0xffffffffu, rs, 1);
            rs += __shfl_xor_sync(0xffffffffu, rs, 2);
            li[hr] = li[hr] * fac + rs;
            mi[hr] = mnew;
#pragma unroll
            for (int na = 0; na < 8; na++) {
                accO[na][2 * hr] *= fac;
                accO[na][2 * hr + 1] *= fac;
            }
        }
        __syncwarp();  // P smem is warp-private; order STS->LDS

        // ---- PV (3xTF32), P from smem as A-fragments ----
#pragma unroll
        for (int ks = 0; ks < 8; ks++) {
            const int t0 = ks * 8;
            uint32_t ph[4], pl[4];
            ph[0] = __float_as_uint(Ph[r0 * 68 + t0 + q4]);
            ph[1] = __float_as_uint(Ph[(r0 + 8) * 68 + t0 + q4]);
            ph[2] = __float_as_uint(Ph[r0 * 68 + t0 + q4 + 4]);
            ph[3] = __float_as_uint(Ph[(r0 + 8) * 68 + t0 + q4 + 4]);
            pl[0] = __float_as_uint(Pl[r0 * 68 + t0 + q4]);
            pl[1] = __float_as_uint(Pl[(r0 + 8) * 68 + t0 + q4]);
            pl[2] = __float_as_uint(Pl[r0 * 68 + t0 + q4 + 4]);
            pl[3] = __float_as_uint(Pl[(r0 + 8) * 68 + t0 + q4 + 4]);
#pragma unroll
            for (int na = 0; na < 8; na++) {
                int d = 8 * na + grp;
                uint32_t vh2[2], vl2[2];
                vh2[0] = __float_as_uint(Vh[d * 68 + t0 + q4]);
                vh2[1] = __float_as_uint(Vh[d * 68 + t0 + q4 + 4]);
                vl2[0] = __float_as_uint(Vl[d * 68 + t0 + q4]);
                vl2[1] = __float_as_uint(Vl[d * 68 + t0 + q4 + 4]);
                mma_tf32(accO[na], ph, vh2);
                mma_tf32(accO[na], ph, vl2);
                mma_tf32(accO[na], pl, vh2);
            }
        }
    }

    // ---- epilogue: normalize + write ctx (B,S,D) ----
    const int b = bh >> 4;
    const int h = bh & 15;
    const float inv0 = 1.0f / li[0];
    const float inv1 = 1.0f / li[1];
    const int rg = qb * 128 + r0;
#pragma unroll
    for (int na = 0; na < 8; na++) {
        int col = h * HD + 8 * na + 2 * q4;
        *(float2*)&g_ctx[((size_t)(b * S + rg)) * D + col] =
            make_float2(accO[na][0] * inv0, accO[na][1] * inv0);
        *(float2*)&g_ctx[((size_t)(b * S + rg + 8)) * D + col] =
            make_float2(accO[na][2] * inv1, accO[na][3] * inv1);
    }
}

// ---------------------------------------------------------------------------
extern "C" void kernel_launch(void* const* d_in, const int* in_sizes, int n_in,
                              void* d_out, int out_size) {
    (void)in_sizes; (void)n_in; (void)out_size;
    const float* x    = (const float*)d_in[0];
    // d_in[1] = attn_mask (pure causal; applied analytically)
    const float* cosb = (const float*)d_in[2];
    const float* sinb = (const float*)d_in[3];
    const float* Wqkv = (const float*)d_in[4];
    const float* Wout = (const float*)d_in[5];
    float* out = (float*)d_out;

    float *qkvp, *ctxp;
    cudaGetSymbolAddress((void**)&qkvp, g_qkv);
    cudaGetSymbolAddress((void**)&ctxp, g_ctx);

    cudaFuncSetAttribute(flash2, cudaFuncAttributeMaxDynamicSharedMemorySize,
                         FSMEM_FLOATS * 4);

    // 1) QKV projection (TF32 tensor cores)
    tgemm<0><<<dim3(24, 64), 256>>>(x, Wqkv, qkvp);
    // 2) RoPE + head reshape
    rope_split<<<dim3(S, H / 4, BB), dim3(64, 4)>>>(qkvp, cosb, sinb);
    // 3) Causal flash attention (3xTF32 tensor cores)
    flash2<<<dim3(S / 128, BB * H), 256, FSMEM_FLOATS * 4>>>();
    // 4) Output projection (TF32 tensor cores) -> (S, B, D)
    tgemm<1><<<dim3(8, 64), 256>>>(ctxp, Wout, out);
}

// round 5
// speedup vs baseline: 1.6995x; 1.0290x over previous
#include <cuda_runtime.h>
#include <cstdint>

#define S 2048
#define BB 4
#define D 1024
#define H 16
#define HD 64

// Scratch (device globals — no allocations allowed)
__device__ float g_q[(size_t)BB * H * S * HD];    // 32 MB
__device__ float g_k[(size_t)BB * H * S * HD];    // 32 MB
__device__ float g_v[(size_t)BB * H * S * HD];    // 32 MB
__device__ float g_ctx[(size_t)BB * S * D];       // 32 MB

// ---------------------------------------------------------------------------
// TF32 helpers
// ---------------------------------------------------------------------------
__device__ __forceinline__ float tf32r(float x) {
    uint32_t u;
    asm("cvt.rna.tf32.f32 %0, %1;" : "=r"(u) : "f"(x));
    return __uint_as_float(u);
}

__device__ __forceinline__ void mma_tf32(float* c, const uint32_t* a,
                                         const uint32_t* b) {
    asm volatile(
        "mma.sync.aligned.m16n8k8.row.col.f32.tf32.tf32.f32 "
        "{%0,%1,%2,%3},{%4,%5,%6,%7},{%8,%9},{%0,%1,%2,%3};"
        : "+f"(c[0]), "+f"(c[1]), "+f"(c[2]), "+f"(c[3])
        : "r"(a[0]), "r"(a[1]), "r"(a[2]), "r"(a[3]), "r"(b[0]), "r"(b[1]));
}

// ---------------------------------------------------------------------------
// TF32 tensor-core GEMM, fragment-major smem staging.
// C[m,n] = sum_k A[m,k]*Bw[k,n], M=8192, K=1024.
// MODE 0: A = x (S,B,D); epilogue applies RoPE and scatters to g_q/g_k/g_v.
// MODE 1: A row-major; C = out (S,B,D), N=1024.
// Block 128x128, BK=16, 256 threads (8 warps, warp tile 32m x 64n).
// Fragment layouts (per K-tile, double buffered):
//   Af4[(mt*2+ks)*32+lane] : float4 = {A[mt16+g][8ks+q], A[+8][..],
//                                      A[mt16+g][8ks+q+4], A[+8][..]}
//   Bf2[(ks*16+n8)*32+lane]: float2 = {B[8ks+q][n8*8+g], B[8ks+q+4][..]}
// ---------------------------------------------------------------------------
template <int MODE>
__global__ void __launch_bounds__(256, 2) tgemm(const float* __restrict__ A,
                                                const float* __restrict__ Bw,
                                                float* __restrict__ C,
                                                const float* __restrict__ cosb,
                                                const float* __restrict__ sinb) {
    constexpr int N = (MODE == 0) ? 3 * D : D;
    constexpr int K = D;

    __shared__ float4 Af4[2][512];
    __shared__ float2 Bf2[2][1024];

    const int tid = threadIdx.x;
    const int bm = blockIdx.y, bn = blockIdx.x;
    const int lane = tid & 31, wid = tid >> 5;
    const int grp = lane >> 2, q4 = lane & 3;
    const int mt0 = (wid & 3) * 2;   // first m16-tile of this warp
    const int n80 = (wid >> 2) * 8;  // first n8-tile of this warp

    // ---- A gather setup: 2 fragments per thread (f = tid, tid+256) ----
    const float* arb[2][2];
    int acol[2];
#pragma unroll
    for (int i = 0; i < 2; i++) {
        int f = tid + i * 256;
        int mt = f >> 6, ks = (f >> 5) & 1, l = f & 31;
        int g = l >> 2, q = l & 3;
        int r0 = bm * 128 + mt * 16 + g;
        acol[i] = ks * 8 + q;
        if (MODE == 0) {
            int b0 = r0 >> 11, s0 = r0 & 2047;
            arb[i][0] = A + ((size_t)s0 * BB + b0) * D;
            int r1 = r0 + 8;
            int b1 = r1 >> 11, s1 = r1 & 2047;
            arb[i][1] = A + ((size_t)s1 * BB + b1) * D;
        } else {
            arb[i][0] = A + (size_t)r0 * D;
            arb[i][1] = A + (size_t)(r0 + 8) * D;
        }
    }
    // ---- B gather setup: 4 fragments per thread (f = i*256+tid) ----
    const float* brb[4];
#pragma unroll
    for (int i = 0; i < 4; i++) {
        int f = i * 256 + tid;
        int ks = f >> 9, n8 = (f >> 5) & 15, l = f & 31;
        int g = l >> 2, q = l & 3;
        brb[i] = Bw + (size_t)(ks * 8 + q) * N + bn * 128 + n8 * 8 + g;
    }

    float acc[2][8][4];
#pragma unroll
    for (int i = 0; i < 2; i++)
#pragma unroll
        for (int j = 0; j < 8; j++)
#pragma unroll
            for (int l = 0; l < 4; l++) acc[i][j][l] = 0.0f;

    // ---- prologue: tile 0 -> buffer 0 ----
#pragma unroll
    for (int i = 0; i < 2; i++) {
        float4 v;
        v.x = arb[i][0][acol[i]];
        v.y = arb[i][1][acol[i]];
        v.z = arb[i][0][acol[i] + 4];
        v.w = arb[i][1][acol[i] + 4];
        Af4[0][tid + i * 256] =
            make_float4(tf32r(v.x), tf32r(v.y), tf32r(v.z), tf32r(v.w));
    }
#pragma unroll
    for (int i = 0; i < 4; i++) {
        float2 v;
        v.x = brb[i][0];
        v.y = brb[i][(size_t)4 * N];
        Bf2[0][i * 256 + tid] = make_float2(tf32r(v.x), tf32r(v.y));
    }
    __syncthreads();

    int buf = 0;
    for (int kt = 0; kt < K; kt += 16) {
        float4 pa[2];
        float2 pb[4];
        const bool pf = (kt + 16) < K;
        if (pf) {
#pragma unroll
            for (int i = 0; i < 2; i++) {
                pa[i].x = arb[i][0][kt + 16 + acol[i]];
                pa[i].y = arb[i][1][kt + 16 + acol[i]];
                pa[i].z = arb[i][0][kt + 16 + acol[i] + 4];
                pa[i].w = arb[i][1][kt + 16 + acol[i] + 4];
            }
#pragma unroll
            for (int i = 0; i < 4; i++) {
                pb[i].x = brb[i][(size_t)(kt + 16) * N];
                pb[i].y = brb[i][(size_t)(kt + 20) * N];
            }
        }

        // ---- compute on current buffer ----
#pragma unroll
        for (int ks = 0; ks < 2; ks++) {
            float4 af[2];
            float2 bf[8];
            af[0] = Af4[buf][((mt0 + 0) * 2 + ks) * 32 + lane];
            af[1] = Af4[buf][((mt0 + 1) * 2 + ks) * 32 + lane];
#pragma unroll
            for (int na = 0; na < 8; na++)
                bf[na] = Bf2[buf][(ks * 16 + n80 + na) * 32 + lane];
#pragma unroll
            for (int ma = 0; ma < 2; ma++)
#pragma unroll
                for (int na = 0; na < 8; na++)
                    mma_tf32(acc[ma][na], (const uint32_t*)&af[ma],
                             (const uint32_t*)&bf[na]);
        }

        if (pf) {
            const int nb = buf ^ 1;
#pragma unroll
            for (int i = 0; i < 2; i++)
                Af4[nb][tid + i * 256] = make_float4(
                    tf32r(pa[i].x), tf32r(pa[i].y), tf32r(pa[i].z),
                    tf32r(pa[i].w));
#pragma unroll
            for (int i = 0; i < 4; i++)
                Bf2[nb][i * 256 + tid] =
                    make_float2(tf32r(pb[i].x), tf32r(pb[i].y));
        }
        __syncthreads();
        buf ^= 1;
    }

    // ---- epilogue ----
#pragma unroll
    for (int ma = 0; ma < 2; ma++) {
#pragma unroll
        for (int half = 0; half < 2; half++) {
            int m = bm * 128 + (wid & 3) * 32 + ma * 16 + grp + half * 8;
            int b = m >> 11, s = m & 2047;
#pragma unroll
            for (int na = 0; na < 8; na++) {
                int ncol = bn * 128 + n80 * 8 + na * 8 + (q4 << 1);
                float v0 = acc[ma][na][half * 2 + 0];
                float v1 = acc[ma][na][half * 2 + 1];
                if (MODE == 0) {
                    int sec = ncol >> 10;
                    int e = ncol & 1023;
                    int h = e >> 6, d = e & 63;
                    size_t o = (((size_t)(b * H + h)) * S + s) * HD + d;
                    if (sec == 2) {
                        *(float2*)&g_v[o] = make_float2(v0, v1);
                    } else {
                        float c0 = cosb[s * HD + d];
                        float c1 = cosb[s * HD + d + 1];
                        float s0 = sinb[s * HD + d];
                        float s1 = sinb[s * HD + d + 1];
                        float o0 = v0 * c0 - v1 * s0;
                        float o1 = v1 * c1 + v0 * s1;
                        float* dst = (sec == 0) ? g_q : g_k;
                        *(float2*)&dst[o] = make_float2(o0, o1);
                    }
                } else {
                    *(float2*)&C[((size_t)s * BB + b) * D + ncol] =
                        make_float2(v0, v1);
                }
            }
        }
    }
}

// ---------------------------------------------------------------------------
// Flash attention, causal, 3xTF32 mma.sync, fragment-major smem.
// CTA: 128 q-rows x 64-key tiles, 8 warps, warp owns 16 rows.
// Fragment layouts:
//   qf4[((w*2+hl)*8+ks)*32+lane] float4 (Q a-frags, staged once)
//   kf2[((hl*8+ks)*8+na)*32+lane] float2 = {K[8na+g][8ks+q], K[..][+4]}
//   vf2[((hl*8+ks)*8+na)*32+lane] float2 = {V[8ks+q][8na+g], V[+4][..]}
//   Ph/Pl: [128][68] scalar (pitch 68 => conflict-free scalar a-frag reads)
// ---------------------------------------------------------------------------
#define FL_SMEM_BYTES 200704  // 50176 floats

__global__ void __launch_bounds__(256) flashf() {
    extern __shared__ float fsm[];
    float4* qf4 = (float4*)fsm;             // floats [0, 16384)
    float2* kf2 = (float2*)(fsm + 16384);   // [16384, 24576)
    float2* vf2 = (float2*)(fsm + 24576);   // [24576, 32768)
    float* Ph = fsm + 32768;                // 8704
    float* Pl = fsm + 41472;                // 8704

    const int tid = threadIdx.x;
    const int qb = 15 - (int)blockIdx.x;  // heavy CTAs first
    const int bh = blockIdx.y;
    const int lane = tid & 31, w = tid >> 5;
    const int grp = lane >> 2, q4 = lane & 3;
    const int r0 = w * 16 + grp;

    const float* Qg = g_q + ((size_t)bh * S + (size_t)qb * 128) * HD;
    const float* Kg = g_k + (size_t)bh * S * HD;
    const float* Vg = g_v + (size_t)bh * S * HD;

    // ---- Q fragment fill (once): thread handles (ks=tid>>5, lane=tid&31) ----
    {
        const int ksq = tid >> 5, lq = tid & 31;
        const int gq = lq >> 2, qq = lq & 3;
        const int c0 = ksq * 8 + qq, c1 = c0 + 4;
#pragma unroll
        for (int wf = 0; wf < 8; wf++) {
            int ra = wf * 16 + gq, rb = ra + 8;
            float x0 = Qg[ra * HD + c0] * 0.125f;
            float x1 = Qg[rb * HD + c0] * 0.125f;
            float x2 = Qg[ra * HD + c1] * 0.125f;
            float x3 = Qg[rb * HD + c1] * 0.125f;
            float h0 = tf32r(x0), h1 = tf32r(x1), h2 = tf32r(x2), h3 = tf32r(x3);
            qf4[((wf * 2 + 0) * 8 + ksq) * 32 + lq] = make_float4(h0, h1, h2, h3);
            qf4[((wf * 2 + 1) * 8 + ksq) * 32 + lq] =
                make_float4(tf32r(x0 - h0), tf32r(x1 - h1), tf32r(x2 - h2),
                            tf32r(x3 - h3));
        }
    }

    float accO[8][4];
#pragma unroll
    for (int na = 0; na < 8; na++)
#pragma unroll
        for (int j = 0; j < 4; j++) accO[na][j] = 0.0f;
    float mi[2] = {-1e30f, -1e30f};
    float li[2] = {0.0f, 0.0f};

    // fill roles for K/V
    const int naf = tid >> 5, lf = tid & 31;
    const int gf = lf >> 2, qf = lf & 3;

    const int nkt = 2 * qb + 2;
    for (int kb = 0; kb < nkt; kb++) {
        __syncthreads();  // prev-iter frag reads done before overwrite

        // ---- K/V fragment fill ----
        {
            const float* Kb = Kg + (size_t)kb * 64 * HD;
            const float* Vb = Vg + (size_t)kb * 64 * HD;
            const int t = 8 * naf + gf;  // K token row / V dim col
#pragma unroll
            for (int ks = 0; ks < 8; ks++) {
                int c0 = 8 * ks + qf, c1 = c0 + 4;
                float k0 = Kb[t * HD + c0], k1 = Kb[t * HD + c1];
                float kh0 = tf32r(k0), kh1 = tf32r(k1);
                kf2[((0 * 8 + ks) * 8 + naf) * 32 + lf] = make_float2(kh0, kh1);
                kf2[((1 * 8 + ks) * 8 + naf) * 32 + lf] =
                    make_float2(tf32r(k0 - kh0), tf32r(k1 - kh1));
                float v0 = Vb[c0 * HD + t], v1 = Vb[c1 * HD + t];
                float vh0 = tf32r(v0), vh1 = tf32r(v1);
                vf2[((0 * 8 + ks) * 8 + naf) * 32 + lf] = make_float2(vh0, vh1);
                vf2[((1 * 8 + ks) * 8 + naf) * 32 + lf] =
                    make_float2(tf32r(v0 - vh0), tf32r(v1 - vh1));
            }
        }
        __syncthreads();

        // ---- QK^T (3xTF32) ----
        float accS[8][4];
#pragma unroll
        for (int na = 0; na < 8; na++)
#pragma unroll
            for (int j = 0; j < 4; j++) accS[na][j] = 0.0f;

#pragma unroll
        for (int ks = 0; ks < 8; ks++) {
            float4 ah = qf4[((w * 2 + 0) * 8 + ks) * 32 + lane];
            float4 al = qf4[((w * 2 + 1) * 8 + ks) * 32 + lane];
#pragma unroll
            for (int na = 0; na < 8; na++) {
                float2 bh2 = kf2[((0 * 8 + ks) * 8 + na) * 32 + lane];
                float2 bl2 = kf2[((1 * 8 + ks) * 8 + na) * 32 + lane];
                mma_tf32(accS[na], (const uint32_t*)&ah, (const uint32_t*)&bh2);
                mma_tf32(accS[na], (const uint32_t*)&ah, (const uint32_t*)&bl2);
                mma_tf32(accS[na], (const uint32_t*)&al, (const uint32_t*)&bh2);
            }
        }

        // ---- causal mask ----
        const int rowg0 = qb * 128 + r0;
        const int colbase = kb * 64;
        if (colbase + 63 > rowg0) {
#pragma unroll
            for (int na = 0; na < 8; na++) {
#pragma unroll
                for (int j = 0; j < 2; j++) {
                    int col = colbase + 8 * na + 2 * q4 + j;
                    if (col > rowg0) accS[na][j] = -1e30f;
                    if (col > rowg0 + 8) accS[na][2 + j] = -1e30f;
                }
            }
        }

        // ---- online softmax (row-local within warp quad) ----
#pragma unroll
        for (int hr = 0; hr < 2; hr++) {
            float mx = -1e30f;
#pragma unroll
            for (int na = 0; na < 8; na++)
                mx = fmaxf(mx, fmaxf(accS[na][2 * hr], accS[na][2 * hr + 1]));
            mx = fmaxf(mx, __shfl_xor_sync(0xffffffffu, mx, 1));
            mx = fmaxf(mx, __shfl_xor_sync(0xffffffffu, mx, 2));
            float mnew = fmaxf(mi[hr], mx);
            float fac = __expf(mi[hr] - mnew);
            float rs = 0.0f;
            const int pr = r0 + hr * 8;
#pragma unroll
            for (int na = 0; na < 8; na++) {
                float p0 = __expf(accS[na][2 * hr] - mnew);
                float p1 = __expf(accS[na][2 * hr + 1] - mnew);
                rs += p0 + p1;
                float h0 = tf32r(p0), h1 = tf32r(p1);
                int off = pr * 68 + 8 * na + 2 * q4;
                *(float2*)&Ph[off] = make_float2(h0, h1);
                *(float2*)&Pl[off] = make_float2(tf32r(p0 - h0), tf32r(p1 - h1));
            }
            rs += __shfl_xor_sync(0xffffffffu, rs, 1);
            rs += __shfl_xor_sync(0xffffffffu, rs, 2);
            li[hr] = li[hr] * fac + rs;
            mi[hr] = mnew;
#pragma unroll
            for (int na = 0; na < 8; na++) {
                accO[na][2 * hr] *= fac;
                accO[na][2 * hr + 1] *= fac;
            }
        }
        __syncwarp();  // P smem is warp-private; order STS->LDS

        // ---- PV (3xTF32): A=P scalar reads (pitch 68), B=V frag reads ----
#pragma unroll
        for (int ks = 0; ks < 8; ks++) {
            const int t0 = ks * 8;
            uint32_t ph[4], pl[4];
            ph[0] = __float_as_uint(Ph[r0 * 68 + t0 + q4]);
            ph[1] = __float_as_uint(Ph[(r0 + 8) * 68 + t0 + q4]);
            ph[2] = __float_as_uint(Ph[r0 * 68 + t0 + q4 + 4]);
            ph[3] = __float_as_uint(Ph[(r0 + 8) * 68 + t0 + q4 + 4]);
            pl[0] = __float_as_uint(Pl[r0 * 68 + t0 + q4]);
            pl[1] = __float_as_uint(Pl[(r0 + 8) * 68 + t0 + q4]);
            pl[2] = __float_as_uint(Pl[r0 * 68 + t0 + q4 + 4]);
            pl[3] = __float_as_uint(Pl[(r0 + 8) * 68 + t0 + q4 + 4]);
#pragma unroll
            for (int na = 0; na < 8; na++) {
                float2 vh2 = vf2[((0 * 8 + ks) * 8 + na) * 32 + lane];
                float2 vl2 = vf2[((1 * 8 + ks) * 8 + na) * 32 + lane];
                mma_tf32(accO[na], ph, (const uint32_t*)&vh2);
                mma_tf32(accO[na], ph, (const uint32_t*)&vl2);
                mma_tf32(accO[na], pl, (const uint32_t*)&vh2);
            }
        }
    }

    // ---- epilogue: normalize + write ctx (B,S,D) ----
    const int b = bh >> 4;
    const int h = bh & 15;
    const float inv0 = 1.0f / li[0];
    const float inv1 = 1.0f / li[1];
    const int rg = qb * 128 + r0;
#pragma unroll
    for (int na = 0; na < 8; na++) {
        int col = h * HD + 8 * na + 2 * q4;
        *(float2*)&g_ctx[((size_t)(b * S + rg)) * D + col] =
            make_float2(accO[na][0] * inv0, accO[na][1] * inv0);
        *(float2*)&g_ctx[((size_t)(b * S + rg + 8)) * D + col] =
            make_float2(accO[na][2] * inv1, accO[na][3] * inv1);
    }
}

// ---------------------------------------------------------------------------
extern "C" void kernel_launch(void* const* d_in, const int* in_sizes, int n_in,
                              void* d_out, int out_size) {
    (void)in_sizes; (void)n_in; (void)out_size;
    const float* x    = (const float*)d_in[0];
    // d_in[1] = attn_mask (pure causal; applied analytically)
    const float* cosb = (const float*)d_in[2];
    const float* sinb = (const float*)d_in[3];
    const float* Wqkv = (const float*)d_in[4];
    const float* Wout = (const float*)d_in[5];
    float* out = (float*)d_out;

    float* ctxp;
    cudaGetSymbolAddress((void**)&ctxp, g_ctx);

    cudaFuncSetAttribute(flashf, cudaFuncAttributeMaxDynamicSharedMemorySize,
                         FL_SMEM_BYTES);

    // 1) QKV projection + fused RoPE + head split (TF32 tensor cores)
    tgemm<0><<<dim3(24, 64), 256>>>(x, Wqkv, nullptr, cosb, sinb);
    // 2) Causal flash attention (3xTF32, fragment-major smem)
    flashf<<<dim3(S / 128, BB * H), 256, FL_SMEM_BYTES>>>();
    // 3) Output projection (TF32 tensor cores) -> (S, B, D)
    tgemm<1><<<dim3(8, 64), 256>>>(ctxp, Wout, out, nullptr, nullptr);
}

// round 6
// speedup vs baseline: 2.4357x; 1.4332x over previous
#include <cuda_runtime.h>
#include <cstdint>

#define S 2048
#define BB 4
#define D 1024
#define H 16
#define HD 64

// Scratch (device globals — no allocations allowed)
__device__ float g_q[(size_t)BB * H * S * HD];    // 32 MB
__device__ float g_k[(size_t)BB * H * S * HD];    // 32 MB
__device__ float g_v[(size_t)BB * H * S * HD];    // 32 MB
__device__ float g_ctx[(size_t)BB * S * D];       // 32 MB

// ---------------------------------------------------------------------------
// TF32 / BF16 helpers
// ---------------------------------------------------------------------------
__device__ __forceinline__ float tf32r(float x) {
    uint32_t u;
    asm("cvt.rna.tf32.f32 %0, %1;" : "=r"(u) : "f"(x));
    return __uint_as_float(u);
}

__device__ __forceinline__ void mma_tf32(float* c, const uint32_t* a,
                                         const uint32_t* b) {
    asm volatile(
        "mma.sync.aligned.m16n8k8.row.col.f32.tf32.tf32.f32 "
        "{%0,%1,%2,%3},{%4,%5,%6,%7},{%8,%9},{%0,%1,%2,%3};"
        : "+f"(c[0]), "+f"(c[1]), "+f"(c[2]), "+f"(c[3])
        : "r"(a[0]), "r"(a[1]), "r"(a[2]), "r"(a[3]), "r"(b[0]), "r"(b[1]));
}

__device__ __forceinline__ void mma_bf16(float* c, const uint32_t* a,
                                         const uint32_t* b) {
    asm volatile(
        "mma.sync.aligned.m16n8k16.row.col.f32.bf16.bf16.f32 "
        "{%0,%1,%2,%3},{%4,%5,%6,%7},{%8,%9},{%0,%1,%2,%3};"
        : "+f"(c[0]), "+f"(c[1]), "+f"(c[2]), "+f"(c[3])
        : "r"(a[0]), "r"(a[1]), "r"(a[2]), "r"(a[3]), "r"(b[0]), "r"(b[1]));
}

// hi = truncate-to-bf16 (exact complement), lo = rn-bf16(x - hi)
__device__ __forceinline__ float hif(float a) {
    return __uint_as_float(__float_as_uint(a) & 0xFFFF0000u);
}
__device__ __forceinline__ uint32_t packhi(float a, float b) {
    // {low half = bf16_trunc(a), high half = bf16_trunc(b)}
    return __byte_perm(__float_as_uint(a), __float_as_uint(b), 0x7632);
}
__device__ __forceinline__ uint32_t packlo(float a, float b) {
    float la = a - hif(a), lb = b - hif(b);
    uint32_t r;
    asm("cvt.rn.bf16x2.f32 %0, %1, %2;" : "=r"(r) : "f"(lb), "f"(la));
    return r;
}

// ---------------------------------------------------------------------------
// TF32 tensor-core GEMM (R2-proven loader) + fused RoPE epilogue in MODE 0.
// C[m,n] = sum_k A[m,k]*Bw[k,n], M=8192, K=1024.
// MODE 0: A = x (S,B,D); epilogue applies RoPE and scatters to g_q/g_k/g_v.
// MODE 1: A row-major; C = out (S,B,D), N=1024.
// ---------------------------------------------------------------------------
template <int MODE>
__global__ void __launch_bounds__(256, 2) tgemm(const float* __restrict__ A,
                                                const float* __restrict__ Bw,
                                                float* __restrict__ C,
                                                const float* __restrict__ cosb,
                                                const float* __restrict__ sinb) {
    constexpr int N = (MODE == 0) ? 3 * D : D;
    constexpr int K = D;

    __shared__ float As[2][128][20];
    __shared__ float Bs[2][16][136];

    const int tid = threadIdx.x;
    const int bm = blockIdx.y, bn = blockIdx.x;
    const int lane = tid & 31, wid = tid >> 5;
    const int grp = lane >> 2, q4 = lane & 3;
    const int wm = (wid & 3) * 32;
    const int wn = (wid >> 2) * 64;

    const int arow = tid >> 1;
    const int ak = (tid & 1) << 2;
    const int m_a = bm * 128 + arow;
    const float* Ag;
    if (MODE == 0) {
        int b = m_a >> 11, s = m_a & 2047;
        Ag = A + ((size_t)s * BB + b) * D;
    } else {
        Ag = A + (size_t)m_a * D;
    }

    const int bkr = tid >> 5;
    const int bcol = (tid & 31) << 2;
    const float* Bg = Bw + (size_t)bkr * N + bn * 128 + bcol;

    float acc[2][8][4];
#pragma unroll
    for (int i = 0; i < 2; i++)
#pragma unroll
        for (int j = 0; j < 8; j++)
#pragma unroll
            for (int l = 0; l < 4; l++) acc[i][j][l] = 0.0f;

    {
        float4 a0 = *(const float4*)(Ag + ak);
        float4 a1 = *(const float4*)(Ag + ak + 8);
        float4 b0 = *(const float4*)(Bg);
        float4 b1 = *(const float4*)(Bg + (size_t)8 * N);
        As[0][arow][ak + 0] = tf32r(a0.x);
        As[0][arow][ak + 1] = tf32r(a0.y);
        As[0][arow][ak + 2] = tf32r(a0.z);
        As[0][arow][ak + 3] = tf32r(a0.w);
        As[0][arow][ak + 8] = tf32r(a1.x);
        As[0][arow][ak + 9] = tf32r(a1.y);
        As[0][arow][ak + 10] = tf32r(a1.z);
        As[0][arow][ak + 11] = tf32r(a1.w);
        Bs[0][bkr][bcol + 0] = tf32r(b0.x);
        Bs[0][bkr][bcol + 1] = tf32r(b0.y);
        Bs[0][bkr][bcol + 2] = tf32r(b0.z);
        Bs[0][bkr][bcol + 3] = tf32r(b0.w);
        Bs[0][bkr + 8][bcol + 0] = tf32r(b1.x);
        Bs[0][bkr + 8][bcol + 1] = tf32r(b1.y);
        Bs[0][bkr + 8][bcol + 2] = tf32r(b1.z);
        Bs[0][bkr + 8][bcol + 3] = tf32r(b1.w);
    }
    __syncthreads();

    int buf = 0;
    for (int kt = 0; kt < K; kt += 16) {
        float4 pa0, pa1, pb0, pb1;
        const bool pf = (kt + 16) < K;
        if (pf) {
            pa0 = *(const float4*)(Ag + kt + 16 + ak);
            pa1 = *(const float4*)(Ag + kt + 16 + ak + 8);
            pb0 = *(const float4*)(Bg + (size_t)(kt + 16) * N);
            pb1 = *(const float4*)(Bg + (size_t)(kt + 24) * N);
        }

#pragma unroll
        for (int ks = 0; ks < 2; ks++) {
            const int k0 = ks * 8;
            uint32_t a[2][4], b[8][2];
#pragma unroll
            for (int ma = 0; ma < 2; ma++) {
                int r = wm + ma * 16 + grp;
                a[ma][0] = __float_as_uint(As[buf][r][k0 + q4]);
                a[ma][1] = __float_as_uint(As[buf][r + 8][k0 + q4]);
                a[ma][2] = __float_as_uint(As[buf][r][k0 + q4 + 4]);
                a[ma][3] = __float_as_uint(As[buf][r + 8][k0 + q4 + 4]);
            }
#pragma unroll
            for (int na = 0; na < 8; na++) {
                int c = wn + na * 8 + grp;
                b[na][0] = __float_as_uint(Bs[buf][k0 + q4][c]);
                b[na][1] = __float_as_uint(Bs[buf][k0 + q4 + 4][c]);
            }
#pragma unroll
            for (int ma = 0; ma < 2; ma++)
#pragma unroll
                for (int na = 0; na < 8; na++) mma_tf32(acc[ma][na], a[ma], b[na]);
        }

        if (pf) {
            const int nb = buf ^ 1;
            As[nb][arow][ak + 0] = tf32r(pa0.x);
            As[nb][arow][ak + 1] = tf32r(pa0.y);
            As[nb][arow][ak + 2] = tf32r(pa0.z);
            As[nb][arow][ak + 3] = tf32r(pa0.w);
            As[nb][arow][ak + 8] = tf32r(pa1.x);
            As[nb][arow][ak + 9] = tf32r(pa1.y);
            As[nb][arow][ak + 10] = tf32r(pa1.z);
            As[nb][arow][ak + 11] = tf32r(pa1.w);
            Bs[nb][bkr][bcol + 0] = tf32r(pb0.x);
            Bs[nb][bkr][bcol + 1] = tf32r(pb0.y);
            Bs[nb][bkr][bcol + 2] = tf32r(pb0.z);
            Bs[nb][bkr][bcol + 3] = tf32r(pb0.w);
            Bs[nb][bkr + 8][bcol + 0] = tf32r(pb1.x);
            Bs[nb][bkr + 8][bcol + 1] = tf32r(pb1.y);
            Bs[nb][bkr + 8][bcol + 2] = tf32r(pb1.z);
            Bs[nb][bkr + 8][bcol + 3] = tf32r(pb1.w);
        }
        __syncthreads();
        buf ^= 1;
    }

    // ---- epilogue (MODE 0: fused RoPE + head scatter) ----
#pragma unroll
    for (int ma = 0; ma < 2; ma++) {
#pragma unroll
        for (int half = 0; half < 2; half++) {
            int m = bm * 128 + wm + ma * 16 + grp + half * 8;
            int b = m >> 11, s = m & 2047;
#pragma unroll
            for (int na = 0; na < 8; na++) {
                int ncol = bn * 128 + wn + na * 8 + (q4 << 1);
                float v0 = acc[ma][na][half * 2 + 0];
                float v1 = acc[ma][na][half * 2 + 1];
                if (MODE == 0) {
                    int sec = ncol >> 10;
                    int e = ncol & 1023;
                    int h = e >> 6, d = e & 63;
                    size_t o = (((size_t)(b * H + h)) * S + s) * HD + d;
                    if (sec == 2) {
                        *(float2*)&g_v[o] = make_float2(v0, v1);
                    } else {
                        float c0 = cosb[s * HD + d];
                        float c1 = cosb[s * HD + d + 1];
                        float s0 = sinb[s * HD + d];
                        float s1 = sinb[s * HD + d + 1];
                        float o0 = v0 * c0 - v1 * s0;
                        float o1 = v1 * c1 + v0 * s1;
                        float* dst = (sec == 0) ? g_q : g_k;
                        *(float2*)&dst[o] = make_float2(o0, o1);
                    }
                } else {
                    *(float2*)&C[((size_t)s * BB + b) * D + ncol] =
                        make_float2(v0, v1);
                }
            }
        }
    }
}

// ---------------------------------------------------------------------------
// Flash attention, causal, 3-pass compensated BF16 (m16n8k16).
// CTA: 128 q-rows x 64-key tiles, 8 warps (warp owns 16 rows).
// Smem: qf (uint4 a-frags, hi/lo, filled once), kf/vf (uint2 b-frags, hi/lo,
// padded rows of 33). P never touches smem: exp'd scores -> bf16 a-frags in
// registers (k16 pairing == accumulator column pairing).
// ---------------------------------------------------------------------------
#define FLB_QF_BYTES 32768           // 8w*2hl*4ks*32 lanes * 16B
#define FLB_KF_BYTES 16896           // 64 rows * 33 uint2 * 8B
#define FLB_SMEM (FLB_QF_BYTES + 2 * FLB_KF_BYTES)  // 66560

__global__ void __launch_bounds__(256, 2) flashb() {
    extern __shared__ char fsm[];
    uint4* qf = (uint4*)fsm;
    uint2* kf = (uint2*)(fsm + FLB_QF_BYTES);
    uint2* vf = (uint2*)(fsm + FLB_QF_BYTES + FLB_KF_BYTES);

    const int tid = threadIdx.x;
    const int qb = 15 - (int)blockIdx.x;  // heavy CTAs first
    const int bh = blockIdx.y;
    const int lane = tid & 31, w = tid >> 5;
    const int grp = lane >> 2, q4 = lane & 3;
    const int r0 = w * 16 + grp;

    const float* Qg = g_q + ((size_t)bh * S + (size_t)qb * 128) * HD;
    const float* Kg = g_k + (size_t)bh * S * HD;
    const float* Vg = g_v + (size_t)bh * S * HD;

    // ---- Q fill (once): coalesced float4 LDG -> hi/lo bf16x2 frag STS ----
#pragma unroll
    for (int i = 0; i < 8; i++) {
        int idx = i * 256 + tid;
        int r = idx >> 4, c4 = idx & 15;
        int d0 = c4 * 4;
        float4 qv = *(const float4*)(Qg + r * HD + d0);
        float e0 = qv.x * 0.125f, e1 = qv.y * 0.125f;
        float e2 = qv.z * 0.125f, e3 = qv.w * 0.125f;
        int wq = r >> 4, rl = r & 15, g = rl & 7, rh = rl >> 3;
        int ks = d0 >> 4, k2 = d0 & 15;
        int q = (k2 & 7) >> 1;
        int comp = ((k2 >= 8) ? 2 : 0) + rh;
        uint32_t* bhp = (uint32_t*)&qf[((wq * 2 + 0) * 4 + ks) * 32 + g * 4];
        uint32_t* blp = (uint32_t*)&qf[((wq * 2 + 1) * 4 + ks) * 32 + g * 4];
        bhp[q * 4 + comp] = packhi(e0, e1);
        bhp[(q + 1) * 4 + comp] = packhi(e2, e3);
        blp[q * 4 + comp] = packlo(e0, e1);
        blp[(q + 1) * 4 + comp] = packlo(e2, e3);
    }

    float accO[8][4];
#pragma unroll
    for (int na = 0; na < 8; na++)
#pragma unroll
        for (int j = 0; j < 4; j++) accO[na][j] = 0.0f;
    float mi[2] = {-1e30f, -1e30f};
    float li[2] = {0.0f, 0.0f};

    const int ft = tid >> 2;              // fill: token row 0..63
    const int fd0 = (tid & 3) * 16;       // fill: d chunk base

    const int nkt = 2 * qb + 2;
    for (int kb = 0; kb < nkt; kb++) {
        __syncthreads();  // prev-iter frag reads done before overwrite

        // ---- K fill: b-frags for QK (k = d, n = token) ----
        {
            const float* Kb = Kg + (size_t)kb * 64 * HD;
            const int na = ft >> 3, g = ft & 7;
#pragma unroll
            for (int j = 0; j < 4; j++) {
                int d0 = fd0 + j * 4;
                float4 kv = *(const float4*)(Kb + ft * HD + d0);
                int ks = d0 >> 4, k2 = d0 & 15;
                int q = (k2 & 7) >> 1;
                int comp = (k2 >= 8) ? 1 : 0;
                uint32_t* rh = (uint32_t*)&kf[((0 * 4 + ks) * 8 + na) * 33 + g * 4];
                uint32_t* rl = (uint32_t*)&kf[((1 * 4 + ks) * 8 + na) * 33 + g * 4];
                rh[q * 2 + comp] = packhi(kv.x, kv.y);
                rh[(q + 1) * 2 + comp] = packhi(kv.z, kv.w);
                rl[q * 2 + comp] = packlo(kv.x, kv.y);
                rl[(q + 1) * 2 + comp] = packlo(kv.z, kv.w);
            }
        }
        // ---- V fill: b-frags for PV (k = token, n = d) -> u16 scatter ----
        {
            const float* Vb = Vg + (size_t)kb * 64 * HD;
            int ks = ft >> 4, tk = ft & 15;
            int comp = (tk >= 8) ? 1 : 0;
            int q = (tk & 7) >> 1;
            int hlf = tk & 1;
#pragma unroll
            for (int j = 0; j < 4; j++) {
                int d0 = fd0 + j * 4;
                float4 vv = *(const float4*)(Vb + ft * HD + d0);
                float e[4] = {vv.x, vv.y, vv.z, vv.w};
#pragma unroll
                for (int ei = 0; ei < 4; ei++) {
                    int d = d0 + ei;
                    int na = d >> 3, g = d & 7;
                    uint16_t hb = (uint16_t)(__float_as_uint(e[ei]) >> 16);
                    float lof = e[ei] - hif(e[ei]);
                    uint16_t lb;
                    asm("cvt.rn.bf16.f32 %0, %1;" : "=h"(lb) : "f"(lof));
                    uint16_t* ph =
                        (uint16_t*)&vf[((0 * 4 + ks) * 8 + na) * 33 + g * 4 + q];
                    uint16_t* pl =
                        (uint16_t*)&vf[((1 * 4 + ks) * 8 + na) * 33 + g * 4 + q];
                    ph[comp * 2 + hlf] = hb;
                    pl[comp * 2 + hlf] = lb;
                }
            }
        }
        __syncthreads();

        // ---- QK^T (3x compensated bf16) ----
        float accS[8][4];
#pragma unroll
        for (int na = 0; na < 8; na++)
#pragma unroll
            for (int j = 0; j < 4; j++) accS[na][j] = 0.0f;

#pragma unroll
        for (int ks = 0; ks < 4; ks++) {
            uint4 qh = qf[((w * 2 + 0) * 4 + ks) * 32 + lane];
            uint4 ql = qf[((w * 2 + 1) * 4 + ks) * 32 + lane];
#pragma unroll
            for (int na = 0; na < 8; na++) {
                uint2 kh = kf[((0 * 4 + ks) * 8 + na) * 33 + lane];
                uint2 kl = kf[((1 * 4 + ks) * 8 + na) * 33 + lane];
                mma_bf16(accS[na], (const uint32_t*)&qh, (const uint32_t*)&kh);
                mma_bf16(accS[na], (const uint32_t*)&qh, (const uint32_t*)&kl);
                mma_bf16(accS[na], (const uint32_t*)&ql, (const uint32_t*)&kh);
            }
        }

        // ---- causal mask ----
        const int rowg0 = qb * 128 + r0;
        const int colbase = kb * 64;
        if (colbase + 63 > rowg0) {
#pragma unroll
            for (int na = 0; na < 8; na++) {
#pragma unroll
                for (int j = 0; j < 2; j++) {
                    int col = colbase + 8 * na + 2 * q4 + j;
                    if (col > rowg0) accS[na][j] = -1e30f;
                    if (col > rowg0 + 8) accS[na][2 + j] = -1e30f;
                }
            }
        }

        // ---- online softmax (exp in place; P stays in registers) ----
#pragma unroll
        for (int hr = 0; hr < 2; hr++) {
            float mx = -1e30f;
#pragma unroll
            for (int na = 0; na < 8; na++)
                mx = fmaxf(mx, fmaxf(accS[na][2 * hr], accS[na][2 * hr + 1]));
            mx = fmaxf(mx, __shfl_xor_sync(0xffffffffu, mx, 1));
            mx = fmaxf(mx, __shfl_xor_sync(0xffffffffu, mx, 2));
            float mnew = fmaxf(mi[hr], mx);
            float fac = __expf(mi[hr] - mnew);
            float rs = 0.0f;
#pragma unroll
            for (int na = 0; na < 8; na++) {
                float p0 = __expf(accS[na][2 * hr] - mnew);
                float p1 = __expf(accS[na][2 * hr + 1] - mnew);
                accS[na][2 * hr] = p0;
                accS[na][2 * hr + 1] = p1;
                rs += p0 + p1;
            }
            rs += __shfl_xor_sync(0xffffffffu, rs, 1);
            rs += __shfl_xor_sync(0xffffffffu, rs, 2);
            li[hr] = li[hr] * fac + rs;
            mi[hr] = mnew;
#pragma unroll
            for (int na = 0; na < 8; na++) {
                accO[na][2 * hr] *= fac;
                accO[na][2 * hr + 1] *= fac;
            }
        }

        // ---- PV (3x compensated bf16); A=P built in registers ----
#pragma unroll
        for (int ks = 0; ks < 4; ks++) {
            const float* A0 = accS[2 * ks];
            const float* A1 = accS[2 * ks + 1];
            uint32_t ah[4], al[4];
            ah[0] = packhi(A0[0], A0[1]);
            ah[1] = packhi(A0[2], A0[3]);
            ah[2] = packhi(A1[0], A1[1]);
            ah[3] = packhi(A1[2], A1[3]);
            al[0] = packlo(A0[0], A0[1]);
            al[1] = packlo(A0[2], A0[3]);
            al[2] = packlo(A1[0], A1[1]);
            al[3] = packlo(A1[2], A1[3]);
#pragma unroll
            for (int na = 0; na < 8; na++) {
                uint2 vh = vf[((0 * 4 + ks) * 8 + na) * 33 + lane];
                uint2 vl = vf[((1 * 4 + ks) * 8 + na) * 33 + lane];
                mma_bf16(accO[na], ah, (const uint32_t*)&vh);
                mma_bf16(accO[na], ah, (const uint32_t*)&vl);
                mma_bf16(accO[na], al, (const uint32_t*)&vh);
            }
        }
    }

    // ---- epilogue: normalize + write ctx (B,S,D) ----
    const int b = bh >> 4;
    const int h = bh & 15;
    const float inv0 = 1.0f / li[0];
    const float inv1 = 1.0f / li[1];
    const int rg = qb * 128 + r0;
#pragma unroll
    for (int na = 0; na < 8; na++) {
        int col = h * HD + 8 * na + 2 * q4;
        *(float2*)&g_ctx[((size_t)(b * S + rg)) * D + col] =
            make_float2(accO[na][0] * inv0, accO[na][1] * inv0);
        *(float2*)&g_ctx[((size_t)(b * S + rg + 8)) * D + col] =
            make_float2(accO[na][2] * inv1, accO[na][3] * inv1);
    }
}

// ---------------------------------------------------------------------------
extern "C" void kernel_launch(void* const* d_in, const int* in_sizes, int n_in,
                              void* d_out, int out_size) {
    (void)in_sizes; (void)n_in; (void)out_size;
    const float* x    = (const float*)d_in[0];
    // d_in[1] = attn_mask (pure causal; applied analytically)
    const float* cosb = (const float*)d_in[2];
    const float* sinb = (const float*)d_in[3];
    const float* Wqkv = (const float*)d_in[4];
    const float* Wout = (const float*)d_in[5];
    float* out = (float*)d_out;

    float* ctxp;
    cudaGetSymbolAddress((void**)&ctxp, g_ctx);

    cudaFuncSetAttribute(flashb, cudaFuncAttributeMaxDynamicSharedMemorySize,
                         FLB_SMEM);

    // 1) QKV projection + fused RoPE + head split (TF32 tensor cores)
    tgemm<0><<<dim3(24, 64), 256>>>(x, Wqkv, nullptr, cosb, sinb);
    // 2) Causal flash attention (3x compensated bf16 tensor cores)
    flashb<<<dim3(S / 128, BB * H), 256, FLB_SMEM>>>();
    // 3) Output projection (TF32 tensor cores) -> (S, B, D)
    tgemm<1><<<dim3(8, 64), 256>>>(ctxp, Wout, out, nullptr, nullptr);
}